// round 12
// baseline (speedup 1.0000x reference)
#include <cuda_runtime.h>
#include <math.h>

// Problem constants
#define BQ   4096     // both sides fused: [0,2048)=left, [2048,4096)=right
#define BH   2048
#define LVS  64
#define IND  300
#define M    150
#define M3   450
#define HIDD 50
#define NCC  5
#define VMAX 50000

#define TRT  16       // rows per block (tree + vocab2)
#define VRT  32       // rows per block (vocab GEMM)

// Scratch (uninitialized __device__ globals: no runtime allocation)
__device__ __align__(16) float g_hc[VMAX * 2 * M];   // 60 MB: [v][0:150]=h, [150:300]=c
__device__ __align__(16) float g_iouh[VMAX * M3];    // 90 MB: h(v)@Wiouh
__device__ __align__(16) float g_fc[VMAX * M];       // 30 MB: sig(h(v)@Wfh+bfh)*c(v)
__device__ __align__(16) float g_hA[BQ * (LVS / 2) * M];
__device__ __align__(16) float g_cA[BQ * (LVS / 2) * M];
__device__ __align__(16) float g_hB[BQ * (LVS / 4) * M];
__device__ __align__(16) float g_cB[BQ * (LVS / 4) * M];
__device__ __align__(16) float g_WP[M * 3 * 256];    // tree weights plane-split (750 fused cols)
__device__ __align__(16) float g_WP2[M * 3 * 256];   // vocab2 weights plane-split (600 fused cols)
__device__ __align__(16) float g_WdupX[IND * 900];   // vocab: [k][450 cols x2]

__device__ __forceinline__ float sigf(float x)  { return 1.0f / (1.0f + __expf(-x)); }
__device__ __forceinline__ float tanhf_(float x){ return 1.0f - 2.0f / (__expf(2.0f * x) + 1.0f); }

// ---- packed f32x2 helpers (sm_100+) --------------------------------------
__device__ __forceinline__ void ffma2(unsigned long long& acc,
                                      unsigned long long a,
                                      unsigned long long b) {
    asm("fma.rn.f32x2 %0, %1, %2, %0;" : "+l"(acc) : "l"(a), "l"(b));
}
__device__ __forceinline__ unsigned long long pack2(float x, float y) {
    unsigned long long r;
    asm("mov.b64 %0, {%1, %2};" : "=l"(r) : "f"(x), "f"(y));
    return r;
}
__device__ __forceinline__ float2 unpack2(unsigned long long v) {
    float2 f;
    asm("mov.b64 {%0, %1}, %2;" : "=f"(f.x), "=f"(f.y) : "l"(v));
    return f;
}

// ---------------------------------------------------------------------------
// Prep: plane-split weights.
//   tree:  Wfused[k][c]  = (c<450) ? Wiouh[k][c] : Wfh[k][(c-450)%150]   (750 cols)
//   vocab2:Wfused2[k][c] = (c<450) ? Wiouh[k][c] : Wfh[k][c-450]         (600 cols)
//   vocab: g_WdupX[k][2c..2c+1] = Wioux[k][c]
// ---------------------------------------------------------------------------
__global__ void __launch_bounds__(256) prep_kernel(
    const float* __restrict__ Wiouh, const float* __restrict__ Wfh,
    const float* __restrict__ Wioux)
{
    int idx = blockIdx.x * 256 + threadIdx.x;
    const int NT  = M * 750;          // 112500
    const int NT2 = M * 600;          // 90000
    const int NX  = IND * M3;         // 135000
    if (idx < NT) {
        int k = idx / 750, c = idx - k * 750;
        float w = (c < M3) ? Wiouh[k * M3 + c]
                           : Wfh[k * M + (c >= 600 ? c - 600 : c - 450)];
        int t = c / 3, p = c - 3 * t;
        g_WP[(k * 3 + p) * 256 + t] = w;
    } else if (idx < NT + NT2) {
        int j = idx - NT;
        int k = j / 600, c = j - k * 600;
        float w = (c < M3) ? Wiouh[k * M3 + c] : Wfh[k * M + (c - 450)];
        int t = c / 3, p = c - 3 * t;
        g_WP2[(k * 3 + p) * 256 + t] = w;
    } else if (idx < NT + NT2 + NX) {
        int j = idx - NT - NT2;
        int k = j / M3, c = j - k * M3;
        float w = Wioux[k * M3 + c];
        g_WdupX[k * 900 + 2 * c]     = w;
        g_WdupX[k * 900 + 2 * c + 1] = w;
    }
}

// ---------------------------------------------------------------------------
// Vocab GEMM + gates fused: iou = emb[v]@Wioux + bioux + biouh (staged in
// smem), then h,c gates -> g_hc[v]. 256 threads, 32 rows.
// ---------------------------------------------------------------------------
__global__ void __launch_bounds__(256, 2) vocab_kernel(
    const float* __restrict__ emb,
    const float* __restrict__ bx, const float* __restrict__ bhh,
    float* __restrict__ hc, int V)
{
    extern __shared__ __align__(16) float sm[];
    float* xs = sm;                    // [k*36 + rr]

    const int t = threadIdx.x;
    const int base = blockIdx.x * VRT;

    for (int idx = t; idx < VRT * IND; idx += 256) {
        int rr = idx / IND, k = idx - rr * IND;
        int row = base + rr;
        if (row >= V) row = V - 1;
        xs[k * 36 + rr] = emb[row * IND + k];
    }
    __syncthreads();

    unsigned long long a0[16], a1[16];
#pragma unroll
    for (int i = 0; i < 16; i++) { a0[i] = 0ull; a1[i] = 0ull; }

    const bool has1 = (t + 256) < M3;   // t < 194
    const float* __restrict__ wbase0 = g_WdupX + 2 * t;
    const float* __restrict__ wbase1 = g_WdupX + (has1 ? 2 * (t + 256) : 0);

#pragma unroll 2
    for (int k = 0; k < IND; k++) {
        unsigned long long pw0 = *reinterpret_cast<const unsigned long long*>(wbase0 + k * 900);
        unsigned long long pw1 = *reinterpret_cast<const unsigned long long*>(wbase1 + k * 900);
        const ulonglong2* xp = reinterpret_cast<const ulonglong2*>(xs + k * 36);
#pragma unroll
        for (int p = 0; p < 8; p++) {
            ulonglong2 v = xp[p];                 // rows 4p..4p+3
            ffma2(a0[2 * p],     v.x, pw0);
            ffma2(a0[2 * p + 1], v.y, pw0);
            ffma2(a1[2 * p],     v.x, pw1);
            ffma2(a1[2 * p + 1], v.y, pw1);
        }
    }
    __syncthreads();   // xs consumed; reuse sm as iou[rr][452]

    float b0 = bx[t] + bhh[t];
    float b1 = has1 ? (bx[t + 256] + bhh[t + 256]) : 0.f;
#pragma unroll
    for (int pr = 0; pr < 16; pr++) {
        float2 v0 = unpack2(a0[pr]);
        sm[(2 * pr) * 452 + t]     = v0.x + b0;
        sm[(2 * pr + 1) * 452 + t] = v0.y + b0;
        if (has1) {
            float2 v1 = unpack2(a1[pr]);
            sm[(2 * pr) * 452 + t + 256]     = v1.x + b1;
            sm[(2 * pr + 1) * 452 + t + 256] = v1.y + b1;
        }
    }
    __syncthreads();

    for (int idx = t; idx < VRT * M; idx += 256) {
        int rr = idx / M, j = idx - rr * M;
        int row = base + rr;
        if (row < V) {
            const float* r = sm + rr * 452;
            float iv = sigf(r[j]);
            float ov = sigf(r[j + M]);
            float uv = tanhf_(r[j + 2 * M]);
            float cv = iv * uv;
            float hv = ov * tanhf_(cv);
            hc[row * 2 * M + j]     = hv;
            hc[row * 2 * M + M + j] = cv;
        }
    }
}

// ---------------------------------------------------------------------------
// Vocab2 GEMM (256 thr, 16 rows, 3 slots/thread, 3 blocks/SM):
//   [0,450):  iouh[v][c] = h(v)@Wiouh[:,c]
//   [450,600):fc[v][c']  = sig(h(v)@Wfh[:,c'] + bfh[c']) * c(v)
// ---------------------------------------------------------------------------
__global__ void __launch_bounds__(256, 3) vocab2_kernel(
    const float* __restrict__ hc,
    float* __restrict__ iouh, float* __restrict__ fcout,
    const float* __restrict__ bfh, int V)
{
    __shared__ __align__(16) float sm[9728];   // tile 3000 fl, then res 16x604
    const int t = threadIdx.x;
    const int base = blockIdx.x * TRT;

    float* HT = sm;            // [k*20 + rr]
    for (int idx = t; idx < TRT * M; idx += 256) {
        int rr = idx / M, k = idx - rr * M;
        int row = base + rr;
        if (row >= V) row = V - 1;
        HT[k * 20 + rr] = hc[row * 2 * M + k];
    }
    __syncthreads();

    const int slot0 = 3 * t;
    const bool active = slot0 < 600;
    const float* __restrict__ wp = g_WP2 + (active ? t : 0);

    unsigned long long a0[8], a1[8], a2[8];
#pragma unroll
    for (int i = 0; i < 8; i++) { a0[i] = 0ull; a1[i] = 0ull; a2[i] = 0ull; }

#pragma unroll 2
    for (int k = 0; k < M; k++) {
        const float* wk = wp + k * 768;
        float w0 = wk[0];
        float w1 = wk[256];
        float w2 = wk[512];
        unsigned long long pw0 = pack2(w0, w0);
        unsigned long long pw1 = pack2(w1, w1);
        unsigned long long pw2 = pack2(w2, w2);
        const ulonglong2* tp = reinterpret_cast<const ulonglong2*>(HT + k * 20);
#pragma unroll
        for (int p = 0; p < 4; p++) {
            ulonglong2 v = tp[p];
            ffma2(a0[2 * p],     v.x, pw0);
            ffma2(a0[2 * p + 1], v.y, pw0);
            ffma2(a1[2 * p],     v.x, pw1);
            ffma2(a1[2 * p + 1], v.y, pw1);
            ffma2(a2[2 * p],     v.x, pw2);
            ffma2(a2[2 * p + 1], v.y, pw2);
        }
    }
    __syncthreads();   // tile consumed; reuse sm as res[rr][604]

    if (active) {
#pragma unroll
        for (int p = 0; p < 8; p++) {
            float2 v0 = unpack2(a0[p]);
            float2 v1 = unpack2(a1[p]);
            float2 v2 = unpack2(a2[p]);
            float* r0 = sm + (2 * p) * 604;
            float* r1 = sm + (2 * p + 1) * 604;
            r0[slot0]     = v0.x;  r1[slot0]     = v0.y;
            r0[slot0 + 1] = v1.x;  r1[slot0 + 1] = v1.y;
            r0[slot0 + 2] = v2.x;  r1[slot0 + 2] = v2.y;
        }
    }
    __syncthreads();

    for (int idx = t; idx < TRT * M3; idx += 256) {
        int rr = idx / M3, j = idx - rr * M3;
        int row = base + rr;
        if (row < V) iouh[row * M3 + j] = sm[rr * 604 + j];
    }
    for (int idx = t; idx < TRT * M; idx += 256) {
        int rr = idx / M, j = idx - rr * M;
        int row = base + rr;
        if (row < V) {
            float f = sigf(sm[rr * 604 + 450 + j] + bfh[j]);
            fcout[row * M + j] = f * hc[row * 2 * M + M + j];
        }
    }
}

// ---------------------------------------------------------------------------
// Tree level kernel — 256 thr, 16 output rows, 3 slots/thread, 3 blocks/SM.
// LEAF=true (level 2): children (level-1 states) are computed INLINE from
// token gathers (iouh/fc) + leaf gates; child c kept in smem CC region.
// LEAF=false (levels 3..6): children read from h_in/c_in as before.
// Fused 750 cols: [0,450)=iou(hs), [450,600)=f0, [600,750)=f1.
// dyn smem: 12096 fl (+ 4864 fl CC when LEAF) -> 48384 / 67840 B.
// ---------------------------------------------------------------------------
template <bool LEAF>
__global__ void __launch_bounds__(256, 3) tree_kernel(
    const float* __restrict__ h_in, const float* __restrict__ c_in,
    const int* __restrict__ ltok, const int* __restrict__ rtok,
    const float* __restrict__ iouh, const float* __restrict__ fcv,
    float* __restrict__ h_out, float* __restrict__ c_out,
    const float* __restrict__ biouh, const float* __restrict__ bfh)
{
    extern __shared__ __align__(16) float sm[];
    const int t = threadIdx.x;
    const int base = blockIdx.x * TRT;

    float* HS = sm;            // [k*20 + rr]
    float* H0 = sm + 3000;
    float* H1 = sm + 6000;
    float* CC = sm + 12096;    // LEAF only: [ch*152 + k], 32 children

    if (LEAF) {
        // Compute 32 level-1 children inline: crow = 2*base + ch
        for (int idx = t; idx < 2 * TRT * M; idx += 256) {
            int ch = idx / M, k = idx - ch * M;
            int crow = 2 * base + ch;
            int q = crow >> 5, n = crow & 31;
            const int* toks = (q < BH) ? (ltok + q * LVS) : (rtok + (q - BH) * LVS);
            int t0 = toks[2 * n], t1 = toks[2 * n + 1];
            const float* i0 = iouh + t0 * M3;
            const float* i1 = iouh + t1 * M3;
            float iv = sigf(i0[k] + i1[k] + biouh[k]);
            float ov = sigf(i0[k + M] + i1[k + M] + biouh[k + M]);
            float uv = tanhf_(i0[k + 2 * M] + i1[k + 2 * M] + biouh[k + 2 * M]);
            float cv = iv * uv + fcv[t0 * M + k] + fcv[t1 * M + k];
            float hv = ov * tanhf_(cv);
            int rr = ch >> 1;
            if (ch & 1) H1[k * 20 + rr] = hv; else H0[k * 20 + rr] = hv;
            CC[ch * 152 + k] = cv;
        }
        __syncthreads();
        for (int idx = t; idx < TRT * M; idx += 256) {
            int rr = idx / M, k = idx - rr * M;
            HS[k * 20 + rr] = H0[k * 20 + rr] + H1[k * 20 + rr];
        }
    } else {
        for (int idx = t; idx < TRT * M; idx += 256) {
            int rr = idx / M, k = idx - rr * M;
            int orow = base + rr;
            float a = h_in[(2 * orow) * M + k];
            float b = h_in[(2 * orow + 1) * M + k];
            HS[k * 20 + rr] = a + b;
            H0[k * 20 + rr] = a;
            H1[k * 20 + rr] = b;
        }
    }
    __syncthreads();

    const int slot0 = 3 * t;
    const bool active = slot0 < 750;
    const int region = (slot0 < 450) ? 0 : ((slot0 < 600) ? 1 : 2);
    const float* tile = (region == 0) ? HS : ((region == 1) ? H0 : H1);
    const float* __restrict__ wp = g_WP + (active ? t : 0);

    unsigned long long a0[8], a1[8], a2[8];
#pragma unroll
    for (int i = 0; i < 8; i++) { a0[i] = 0ull; a1[i] = 0ull; a2[i] = 0ull; }

#pragma unroll 2
    for (int k = 0; k < M; k++) {
        const float* wk = wp + k * 768;
        float w0 = wk[0];
        float w1 = wk[256];
        float w2 = wk[512];
        unsigned long long pw0 = pack2(w0, w0);
        unsigned long long pw1 = pack2(w1, w1);
        unsigned long long pw2 = pack2(w2, w2);
        const ulonglong2* tp = reinterpret_cast<const ulonglong2*>(tile + k * 20);
#pragma unroll
        for (int p = 0; p < 4; p++) {
            ulonglong2 v = tp[p];                 // rows 4p..4p+3 (broadcast)
            ffma2(a0[2 * p],     v.x, pw0);
            ffma2(a0[2 * p + 1], v.y, pw0);
            ffma2(a1[2 * p],     v.x, pw1);
            ffma2(a1[2 * p + 1], v.y, pw1);
            ffma2(a2[2 * p],     v.x, pw2);
            ffma2(a2[2 * p + 1], v.y, pw2);
        }
    }
    __syncthreads();   // tiles fully consumed; reuse sm[0,12096) as res[rr][756]

    if (active) {
        float bb0, bb1, bb2;
        if (region == 0)      { bb0 = biouh[slot0];     bb1 = biouh[slot0 + 1]; bb2 = biouh[slot0 + 2]; }
        else if (region == 1) { bb0 = bfh[slot0 - 450]; bb1 = bfh[slot0 - 449]; bb2 = bfh[slot0 - 448]; }
        else                  { bb0 = bfh[slot0 - 600]; bb1 = bfh[slot0 - 599]; bb2 = bfh[slot0 - 598]; }
#pragma unroll
        for (int p = 0; p < 8; p++) {
            float2 v0 = unpack2(a0[p]);
            float2 v1 = unpack2(a1[p]);
            float2 v2 = unpack2(a2[p]);
            float* r0 = sm + (2 * p) * 756;
            float* r1 = sm + (2 * p + 1) * 756;
            r0[slot0]     = v0.x + bb0;  r1[slot0]     = v0.y + bb0;
            r0[slot0 + 1] = v1.x + bb1;  r1[slot0 + 1] = v1.y + bb1;
            r0[slot0 + 2] = v2.x + bb2;  r1[slot0 + 2] = v2.y + bb2;
        }
    }
    __syncthreads();

    for (int idx = t; idx < TRT * M; idx += 256) {
        int rr = idx / M, j = idx - rr * M;
        const float* r = sm + rr * 756;
        float iv = sigf(r[j]);
        float ov = sigf(r[j + 150]);
        float uv = tanhf_(r[j + 300]);
        float f0 = sigf(r[450 + j]);
        float f1 = sigf(r[600 + j]);
        int orow = base + rr;
        float c0, c1;
        if (LEAF) {
            c0 = CC[(2 * rr) * 152 + j];
            c1 = CC[(2 * rr + 1) * 152 + j];
        } else {
            c0 = c_in[(2 * orow) * M + j];
            c1 = c_in[(2 * orow + 1) * M + j];
        }
        float cv = iv * uv + f0 * c0 + f1 * c1;
        float hv = ov * tanhf_(cv);
        c_out[orow * M + j] = cv;
        h_out[orow * M + j] = hv;
    }
}

// ---------------------------------------------------------------------------
// Classifier.
// ---------------------------------------------------------------------------
__global__ void __launch_bounds__(64) cls_kernel(
    const float* __restrict__ hfin,
    const float* __restrict__ Wh, const float* __restrict__ bh,
    const float* __restrict__ Wp, const float* __restrict__ bp,
    float* __restrict__ out)
{
    __shared__ float vec[2 * M];
    __shared__ float mid[HIDD];
    __shared__ float logits[NCC];

    const int q = blockIdx.x;
    const int t = threadIdx.x;
    const float* lh = hfin + q * M;
    const float* rh = hfin + (BH + q) * M;

    for (int j = t; j < M; j += 64) {
        float a = lh[j], b = rh[j];
        vec[j]     = a * b;
        vec[M + j] = fabsf(a - b);
    }
    __syncthreads();

    if (t < HIDD) {
        float s = bh[t];
        for (int j = 0; j < 2 * M; j++) s += vec[j] * Wh[j * HIDD + t];
        mid[t] = sigf(s);
    }
    __syncthreads();

    if (t < NCC) {
        float s = bp[t];
        for (int h = 0; h < HIDD; h++) s += mid[h] * Wp[h * NCC + t];
        logits[t] = s;
    }
    __syncthreads();

    if (t == 0) {
        float mx = logits[0];
        for (int c = 1; c < NCC; c++) mx = fmaxf(mx, logits[c]);
        float sum = 0.f;
        for (int c = 0; c < NCC; c++) sum += expf(logits[c] - mx);
        float lse = mx + logf(sum);
        for (int c = 0; c < NCC; c++) out[q * NCC + c] = logits[c] - lse;
    }
}

// ---------------------------------------------------------------------------
extern "C" void kernel_launch(void* const* d_in, const int* in_sizes, int n_in,
                              void* d_out, int out_size)
{
    (void)n_in; (void)out_size;
    const int*   ltok  = (const int*)d_in[0];
    const int*   rtok  = (const int*)d_in[1];
    const float* emb   = (const float*)d_in[2];
    const float* Wioux = (const float*)d_in[3];
    const float* bioux = (const float*)d_in[4];
    const float* Wiouh = (const float*)d_in[5];
    const float* biouh = (const float*)d_in[6];
    // d_in[7] = Wfx, d_in[8] = bfx : unused by the reference computation
    const float* Wfh   = (const float*)d_in[9];
    const float* bfh   = (const float*)d_in[10];
    const float* Wh    = (const float*)d_in[11];
    const float* bh    = (const float*)d_in[12];
    const float* Wp    = (const float*)d_in[13];
    const float* bp    = (const float*)d_in[14];
    float* out = (float*)d_out;

    int V = in_sizes[2] / IND;
    if (V > VMAX) V = VMAX;

    void* p;
    float *hA, *cA, *hB, *cB, *hc, *iouh, *fc;
    cudaGetSymbolAddress(&p, g_hc);   hc   = (float*)p;
    cudaGetSymbolAddress(&p, g_iouh); iouh = (float*)p;
    cudaGetSymbolAddress(&p, g_fc);   fc   = (float*)p;
    cudaGetSymbolAddress(&p, g_hA); hA = (float*)p;
    cudaGetSymbolAddress(&p, g_cA); cA = (float*)p;
    cudaGetSymbolAddress(&p, g_hB); hB = (float*)p;
    cudaGetSymbolAddress(&p, g_cB); cB = (float*)p;

    const int vocab_smem = 14464 * 4;   // 57856 B
    const int tree_smem  = 12096 * 4;   // 48384 B
    const int leaf_smem  = 16960 * 4;   // 67840 B
    static int attr_done = 0;
    if (!attr_done) {
        cudaFuncSetAttribute(vocab_kernel, cudaFuncAttributeMaxDynamicSharedMemorySize, vocab_smem);
        cudaFuncSetAttribute(tree_kernel<true>,  cudaFuncAttributeMaxDynamicSharedMemorySize, leaf_smem);
        cudaFuncSetAttribute(tree_kernel<false>, cudaFuncAttributeMaxDynamicSharedMemorySize, tree_smem);
        cudaFuncSetAttribute(tree_kernel<true>,  cudaFuncAttributePreferredSharedMemoryCarveout, 100);
        cudaFuncSetAttribute(tree_kernel<false>, cudaFuncAttributePreferredSharedMemoryCarveout, 100);
        cudaFuncSetAttribute(vocab2_kernel, cudaFuncAttributePreferredSharedMemoryCarveout, 100);
        attr_done = 1;
    }

    // 0) Weight layout prep
    prep_kernel<<<(M * 750 + M * 600 + IND * M3 + 255) / 256, 256>>>(Wiouh, Wfh, Wioux);

    // 1) Vocab GEMM + fused gates: g_hc[v] = (h(v), c(v))
    vocab_kernel<<<(V + VRT - 1) / VRT, 256, vocab_smem>>>(emb, bioux, biouh, hc, V);

    // 2) Vocab2 GEMM: iouh[v] = h(v)@Wiouh ; fc[v] = sig(h(v)@Wfh+bfh)*c(v)
    vocab2_kernel<<<(V + TRT - 1) / TRT, 256>>>(hc, iouh, fc, bfh, V);

    // 3) Tree level 2 with INLINE level-1 (leaf) children from token gathers
    tree_kernel<true><<<(BQ * (LVS / 4)) / TRT, 256, leaf_smem>>>(
        nullptr, nullptr, ltok, rtok, iouh, fc, hA, cA, biouh, bfh);

    // 4) Tree levels 3..6, ping-pong A <-> B
    const float* hin = hA; const float* cin = cA;
    float* ho = hB; float* co = cB;
    for (int n_out = LVS / 8; n_out >= 1; n_out >>= 1) {
        tree_kernel<false><<<(BQ * n_out) / TRT, 256, tree_smem>>>(
            hin, cin, nullptr, nullptr, nullptr, nullptr, ho, co, biouh, bfh);
        const float* th = hin; const float* tc = cin;
        hin = ho; cin = co;
        ho = (float*)th; co = (float*)tc;
    }
    // 4 swaps: final 4096x150 state pointed to by hin

    // 5) Classifier
    cls_kernel<<<BH, 64>>>(hin, Wh, bh, Wp, bp, out);
}

// round 13
// speedup vs baseline: 1.1186x; 1.1186x over previous
#include <cuda_runtime.h>
#include <math.h>

// Problem constants
#define BQ   4096     // both sides fused: [0,2048)=left, [2048,4096)=right
#define BH   2048
#define LVS  64
#define IND  300
#define M    150
#define M3   450
#define HIDD 50
#define NCC  5
#define VMAX 50000

#define TRT  16       // rows per block (tree + vocab2)
#define VRT  32       // rows per block (vocab GEMM)

// Scratch (uninitialized __device__ globals: no runtime allocation)
__device__ __align__(16) float g_hc[VMAX * 2 * M];   // 60 MB: [v][0:150]=h, [150:300]=c
__device__ __align__(16) float g_iouh[VMAX * M3];    // 90 MB: h(v)@Wiouh
__device__ __align__(16) float g_fc[VMAX * M];       // 30 MB: sig(h(v)@Wfh+bfh)*c(v)
__device__ __align__(16) float g_hA[BQ * (LVS / 2) * M];
__device__ __align__(16) float g_cA[BQ * (LVS / 2) * M];
__device__ __align__(16) float g_hB[BQ * (LVS / 4) * M];
__device__ __align__(16) float g_cB[BQ * (LVS / 4) * M];
__device__ __align__(16) float g_WP[M * 3 * 256];    // tree weights plane-split (750 fused cols)
__device__ __align__(16) float g_WP2[M * 640];       // vocab2 weights 2-plane split (600 fused cols, stride 320)
__device__ __align__(16) float g_WdupX[IND * 900];   // vocab: [k][450 cols x2]

__device__ __forceinline__ float sigf(float x)  { return 1.0f / (1.0f + __expf(-x)); }
__device__ __forceinline__ float tanhf_(float x){ return 1.0f - 2.0f / (__expf(2.0f * x) + 1.0f); }

// ---- packed f32x2 helpers (sm_100+) --------------------------------------
__device__ __forceinline__ void ffma2(unsigned long long& acc,
                                      unsigned long long a,
                                      unsigned long long b) {
    asm("fma.rn.f32x2 %0, %1, %2, %0;" : "+l"(acc) : "l"(a), "l"(b));
}
__device__ __forceinline__ unsigned long long pack2(float x, float y) {
    unsigned long long r;
    asm("mov.b64 %0, {%1, %2};" : "=l"(r) : "f"(x), "f"(y));
    return r;
}
__device__ __forceinline__ float2 unpack2(unsigned long long v) {
    float2 f;
    asm("mov.b64 {%0, %1}, %2;" : "=f"(f.x), "=f"(f.y) : "l"(v));
    return f;
}

// ---------------------------------------------------------------------------
// Prep: plane-split weights.
//   tree:   Wfused[k][c]  = (c<450) ? Wiouh[k][c] : Wfh[k][(c-450)%150]  (750 cols)
//           g_WP[(k*3+p)*256 + t], c = 3t+p
//   vocab2: Wfused2[k][c] = (c<450) ? Wiouh[k][c] : Wfh[k][c-450]        (600 cols)
//           g_WP2[(k*2+p)*320 + t], c = 2t+p
//   vocab:  g_WdupX[k][2c..2c+1] = Wioux[k][c]
// ---------------------------------------------------------------------------
__global__ void __launch_bounds__(256) prep_kernel(
    const float* __restrict__ Wiouh, const float* __restrict__ Wfh,
    const float* __restrict__ Wioux)
{
    int idx = blockIdx.x * 256 + threadIdx.x;
    const int NT  = M * 750;          // 112500
    const int NT2 = M * 600;          // 90000
    const int NX  = IND * M3;         // 135000
    if (idx < NT) {
        int k = idx / 750, c = idx - k * 750;
        float w = (c < M3) ? Wiouh[k * M3 + c]
                           : Wfh[k * M + (c >= 600 ? c - 600 : c - 450)];
        int t = c / 3, p = c - 3 * t;
        g_WP[(k * 3 + p) * 256 + t] = w;
    } else if (idx < NT + NT2) {
        int j = idx - NT;
        int k = j / 600, c = j - k * 600;
        float w = (c < M3) ? Wiouh[k * M3 + c] : Wfh[k * M + (c - 450)];
        int t = c >> 1, p = c & 1;
        g_WP2[(k * 2 + p) * 320 + t] = w;
    } else if (idx < NT + NT2 + NX) {
        int j = idx - NT - NT2;
        int k = j / M3, c = j - k * M3;
        float w = Wioux[k * M3 + c];
        g_WdupX[k * 900 + 2 * c]     = w;
        g_WdupX[k * 900 + 2 * c + 1] = w;
    }
}

// ---------------------------------------------------------------------------
// Vocab GEMM + gates fused: iou = emb[v]@Wioux + bioux + biouh (staged in
// smem), then h,c gates -> g_hc[v]. 256 threads, 32 rows.
// ---------------------------------------------------------------------------
__global__ void __launch_bounds__(256, 2) vocab_kernel(
    const float* __restrict__ emb,
    const float* __restrict__ bx, const float* __restrict__ bhh,
    float* __restrict__ hc, int V)
{
    extern __shared__ __align__(16) float sm[];
    float* xs = sm;                    // [k*36 + rr]

    const int t = threadIdx.x;
    const int base = blockIdx.x * VRT;

    for (int idx = t; idx < VRT * IND; idx += 256) {
        int rr = idx / IND, k = idx - rr * IND;
        int row = base + rr;
        if (row >= V) row = V - 1;
        xs[k * 36 + rr] = emb[row * IND + k];
    }
    __syncthreads();

    unsigned long long a0[16], a1[16];
#pragma unroll
    for (int i = 0; i < 16; i++) { a0[i] = 0ull; a1[i] = 0ull; }

    const bool has1 = (t + 256) < M3;   // t < 194
    const float* __restrict__ wbase0 = g_WdupX + 2 * t;
    const float* __restrict__ wbase1 = g_WdupX + (has1 ? 2 * (t + 256) : 0);

#pragma unroll 2
    for (int k = 0; k < IND; k++) {
        unsigned long long pw0 = *reinterpret_cast<const unsigned long long*>(wbase0 + k * 900);
        unsigned long long pw1 = *reinterpret_cast<const unsigned long long*>(wbase1 + k * 900);
        const ulonglong2* xp = reinterpret_cast<const ulonglong2*>(xs + k * 36);
#pragma unroll
        for (int p = 0; p < 8; p++) {
            ulonglong2 v = xp[p];                 // rows 4p..4p+3
            ffma2(a0[2 * p],     v.x, pw0);
            ffma2(a0[2 * p + 1], v.y, pw0);
            ffma2(a1[2 * p],     v.x, pw1);
            ffma2(a1[2 * p + 1], v.y, pw1);
        }
    }
    __syncthreads();   // xs consumed; reuse sm as iou[rr][452]

    float b0 = bx[t] + bhh[t];
    float b1 = has1 ? (bx[t + 256] + bhh[t + 256]) : 0.f;
#pragma unroll
    for (int pr = 0; pr < 16; pr++) {
        float2 v0 = unpack2(a0[pr]);
        sm[(2 * pr) * 452 + t]     = v0.x + b0;
        sm[(2 * pr + 1) * 452 + t] = v0.y + b0;
        if (has1) {
            float2 v1 = unpack2(a1[pr]);
            sm[(2 * pr) * 452 + t + 256]     = v1.x + b1;
            sm[(2 * pr + 1) * 452 + t + 256] = v1.y + b1;
        }
    }
    __syncthreads();

    for (int idx = t; idx < VRT * M; idx += 256) {
        int rr = idx / M, j = idx - rr * M;
        int row = base + rr;
        if (row < V) {
            const float* r = sm + rr * 452;
            float iv = sigf(r[j]);
            float ov = sigf(r[j + M]);
            float uv = tanhf_(r[j + 2 * M]);
            float cv = iv * uv;
            float hv = ov * tanhf_(cv);
            hc[row * 2 * M + j]     = hv;
            hc[row * 2 * M + M + j] = cv;
        }
    }
}

// ---------------------------------------------------------------------------
// Vocab2 GEMM — 320 threads, 16 rows, 2 slots/thread (cols 2t, 2t+1; 600
// fused cols -> 300/320 threads active = 94% lane util), 16 ull accumulators
// (32 regs) -> 3 blocks/SM at 68-reg cap = 30 warps/SM.
//   [0,450):  iouh[v][c] = h(v)@Wiouh[:,c]
//   [450,600):fc[v][c']  = sig(h(v)@Wfh[:,c'] + bfh[c']) * c(v)
// ---------------------------------------------------------------------------
__global__ void __launch_bounds__(320, 3) vocab2_kernel(
    const float* __restrict__ hc,
    float* __restrict__ iouh, float* __restrict__ fcout,
    const float* __restrict__ bfh, int V)
{
    __shared__ __align__(16) float sm[9728];   // tile 3000 fl, then res 16x604
    const int t = threadIdx.x;
    const int base = blockIdx.x * TRT;

    float* HT = sm;            // [k*20 + rr]
    for (int idx = t; idx < TRT * M; idx += 320) {
        int rr = idx / M, k = idx - rr * M;
        int row = base + rr;
        if (row >= V) row = V - 1;
        HT[k * 20 + rr] = hc[row * 2 * M + k];
    }
    __syncthreads();

    const int slot0 = 2 * t;
    const bool active = slot0 < 600;   // t < 300
    const float* __restrict__ wp = g_WP2 + (active ? t : 0);

    unsigned long long a0[8], a1[8];
#pragma unroll
    for (int i = 0; i < 8; i++) { a0[i] = 0ull; a1[i] = 0ull; }

#pragma unroll 2
    for (int k = 0; k < M; k++) {
        const float* wk = wp + k * 640;
        float w0 = wk[0];
        float w1 = wk[320];
        unsigned long long pw0 = pack2(w0, w0);
        unsigned long long pw1 = pack2(w1, w1);
        const ulonglong2* tp = reinterpret_cast<const ulonglong2*>(HT + k * 20);
#pragma unroll
        for (int p = 0; p < 4; p++) {
            ulonglong2 v = tp[p];
            ffma2(a0[2 * p],     v.x, pw0);
            ffma2(a0[2 * p + 1], v.y, pw0);
            ffma2(a1[2 * p],     v.x, pw1);
            ffma2(a1[2 * p + 1], v.y, pw1);
        }
    }
    __syncthreads();   // tile consumed; reuse sm as res[rr][604]

    if (active) {
#pragma unroll
        for (int p = 0; p < 8; p++) {
            float2 v0 = unpack2(a0[p]);
            float2 v1 = unpack2(a1[p]);
            float* r0 = sm + (2 * p) * 604;
            float* r1 = sm + (2 * p + 1) * 604;
            r0[slot0]     = v0.x;  r1[slot0]     = v0.y;
            r0[slot0 + 1] = v1.x;  r1[slot0 + 1] = v1.y;
        }
    }
    __syncthreads();

    for (int idx = t; idx < TRT * M3; idx += 320) {
        int rr = idx / M3, j = idx - rr * M3;
        int row = base + rr;
        if (row < V) iouh[row * M3 + j] = sm[rr * 604 + j];
    }
    for (int idx = t; idx < TRT * M; idx += 320) {
        int rr = idx / M, j = idx - rr * M;
        int row = base + rr;
        if (row < V) {
            float f = sigf(sm[rr * 604 + 450 + j] + bfh[j]);
            fcout[row * M + j] = f * hc[row * 2 * M + M + j];
        }
    }
}

// ---------------------------------------------------------------------------
// Leaf level (tree level 1) — NO GEMM, float2-vectorized.
//   iou = iouh[t0] + iouh[t1] + biouh ; c = sig(i)tanh(u) + fc[t0]+fc[t1];
// ---------------------------------------------------------------------------
__global__ void __launch_bounds__(256) leaf1_kernel(
    const int* __restrict__ ltok, const int* __restrict__ rtok,
    const float* __restrict__ iouh, const float* __restrict__ fc,
    const float* __restrict__ biouh,
    float* __restrict__ h_out, float* __restrict__ c_out)
{
    int idx = blockIdx.x * 256 + threadIdx.x;     // < BQ*32*75
    int row = idx / 75;
    int j2 = idx - row * 75;                      // float2 index within row
    int j = 2 * j2;
    int q = row >> 5, n = row & 31;
    const int* toks = (q < BH) ? (ltok + q * LVS) : (rtok + (q - BH) * LVS);
    int t0 = toks[2 * n], t1 = toks[2 * n + 1];
    const float2* i0 = reinterpret_cast<const float2*>(iouh + t0 * M3);
    const float2* i1 = reinterpret_cast<const float2*>(iouh + t1 * M3);
    float2 ai = i0[j2],       bi = i1[j2];
    float2 ao = i0[j2 + 75],  bo = i1[j2 + 75];
    float2 au = i0[j2 + 150], bu = i1[j2 + 150];
    float2 f0v = *reinterpret_cast<const float2*>(fc + t0 * M + j);
    float2 f1v = *reinterpret_cast<const float2*>(fc + t1 * M + j);
    float2 bbi = *reinterpret_cast<const float2*>(biouh + j);
    float2 bbo = *reinterpret_cast<const float2*>(biouh + M + j);
    float2 bbu = *reinterpret_cast<const float2*>(biouh + 2 * M + j);

    float2 cv, hv;
    {
        float iv = sigf(ai.x + bi.x + bbi.x);
        float ov = sigf(ao.x + bo.x + bbo.x);
        float uv = tanhf_(au.x + bu.x + bbu.x);
        cv.x = iv * uv + f0v.x + f1v.x;
        hv.x = ov * tanhf_(cv.x);
    }
    {
        float iv = sigf(ai.y + bi.y + bbi.y);
        float ov = sigf(ao.y + bo.y + bbo.y);
        float uv = tanhf_(au.y + bu.y + bbu.y);
        cv.y = iv * uv + f0v.y + f1v.y;
        hv.y = ov * tanhf_(cv.y);
    }
    *reinterpret_cast<float2*>(c_out + row * M + j) = cv;
    *reinterpret_cast<float2*>(h_out + row * M + j) = hv;
}

// ---------------------------------------------------------------------------
// Tree level kernel (levels 2..6) — 256 thr, 16 rows, 3 slots/thread,
// 3 blocks/SM (the verified register-pressure optimum).
// Fused 750 cols: [0,450)=iou(hs), [450,600)=f0, [600,750)=f1.
// ---------------------------------------------------------------------------
__global__ void __launch_bounds__(256, 3) tree_kernel(
    const float* __restrict__ h_in, const float* __restrict__ c_in,
    float* __restrict__ h_out, float* __restrict__ c_out,
    const float* __restrict__ biouh, const float* __restrict__ bfh)
{
    __shared__ __align__(16) float sm[12096];   // 48384 B
    const int t = threadIdx.x;
    const int base = blockIdx.x * TRT;

    float* HS = sm;            // [k*20 + rr]
    float* H0 = sm + 3000;
    float* H1 = sm + 6000;

    for (int idx = t; idx < TRT * M; idx += 256) {
        int rr = idx / M, k = idx - rr * M;
        int orow = base + rr;
        float a = h_in[(2 * orow) * M + k];
        float b = h_in[(2 * orow + 1) * M + k];
        HS[k * 20 + rr] = a + b;
        H0[k * 20 + rr] = a;
        H1[k * 20 + rr] = b;
    }
    __syncthreads();

    const int slot0 = 3 * t;
    const bool active = slot0 < 750;
    const int region = (slot0 < 450) ? 0 : ((slot0 < 600) ? 1 : 2);
    const float* tile = (region == 0) ? HS : ((region == 1) ? H0 : H1);
    const float* __restrict__ wp = g_WP + (active ? t : 0);

    unsigned long long a0[8], a1[8], a2[8];
#pragma unroll
    for (int i = 0; i < 8; i++) { a0[i] = 0ull; a1[i] = 0ull; a2[i] = 0ull; }

#pragma unroll 2
    for (int k = 0; k < M; k++) {
        const float* wk = wp + k * 768;
        float w0 = wk[0];
        float w1 = wk[256];
        float w2 = wk[512];
        unsigned long long pw0 = pack2(w0, w0);
        unsigned long long pw1 = pack2(w1, w1);
        unsigned long long pw2 = pack2(w2, w2);
        const ulonglong2* tp = reinterpret_cast<const ulonglong2*>(tile + k * 20);
#pragma unroll
        for (int p = 0; p < 4; p++) {
            ulonglong2 v = tp[p];                 // rows 4p..4p+3 (broadcast)
            ffma2(a0[2 * p],     v.x, pw0);
            ffma2(a0[2 * p + 1], v.y, pw0);
            ffma2(a1[2 * p],     v.x, pw1);
            ffma2(a1[2 * p + 1], v.y, pw1);
            ffma2(a2[2 * p],     v.x, pw2);
            ffma2(a2[2 * p + 1], v.y, pw2);
        }
    }
    __syncthreads();   // tiles fully consumed; reuse sm as res[rr][756]

    if (active) {
        float bb0, bb1, bb2;
        if (region == 0)      { bb0 = biouh[slot0];     bb1 = biouh[slot0 + 1]; bb2 = biouh[slot0 + 2]; }
        else if (region == 1) { bb0 = bfh[slot0 - 450]; bb1 = bfh[slot0 - 449]; bb2 = bfh[slot0 - 448]; }
        else                  { bb0 = bfh[slot0 - 600]; bb1 = bfh[slot0 - 599]; bb2 = bfh[slot0 - 598]; }
#pragma unroll
        for (int p = 0; p < 8; p++) {
            float2 v0 = unpack2(a0[p]);
            float2 v1 = unpack2(a1[p]);
            float2 v2 = unpack2(a2[p]);
            float* r0 = sm + (2 * p) * 756;
            float* r1 = sm + (2 * p + 1) * 756;
            r0[slot0]     = v0.x + bb0;  r1[slot0]     = v0.y + bb0;
            r0[slot0 + 1] = v1.x + bb1;  r1[slot0 + 1] = v1.y + bb1;
            r0[slot0 + 2] = v2.x + bb2;  r1[slot0 + 2] = v2.y + bb2;
        }
    }
    __syncthreads();

    for (int idx = t; idx < TRT * M; idx += 256) {
        int rr = idx / M, j = idx - rr * M;
        const float* r = sm + rr * 756;
        float iv = sigf(r[j]);
        float ov = sigf(r[j + 150]);
        float uv = tanhf_(r[j + 300]);
        float f0 = sigf(r[450 + j]);
        float f1 = sigf(r[600 + j]);
        int orow = base + rr;
        float c0 = c_in[(2 * orow) * M + j];
        float c1 = c_in[(2 * orow + 1) * M + j];
        float cv = iv * uv + f0 * c0 + f1 * c1;
        float hv = ov * tanhf_(cv);
        c_out[orow * M + j] = cv;
        h_out[orow * M + j] = hv;
    }
}

// ---------------------------------------------------------------------------
// Classifier.
// ---------------------------------------------------------------------------
__global__ void __launch_bounds__(64) cls_kernel(
    const float* __restrict__ hfin,
    const float* __restrict__ Wh, const float* __restrict__ bh,
    const float* __restrict__ Wp, const float* __restrict__ bp,
    float* __restrict__ out)
{
    __shared__ float vec[2 * M];
    __shared__ float mid[HIDD];
    __shared__ float logits[NCC];

    const int q = blockIdx.x;
    const int t = threadIdx.x;
    const float* lh = hfin + q * M;
    const float* rh = hfin + (BH + q) * M;

    for (int j = t; j < M; j += 64) {
        float a = lh[j], b = rh[j];
        vec[j]     = a * b;
        vec[M + j] = fabsf(a - b);
    }
    __syncthreads();

    if (t < HIDD) {
        float s = bh[t];
        for (int j = 0; j < 2 * M; j++) s += vec[j] * Wh[j * HIDD + t];
        mid[t] = sigf(s);
    }
    __syncthreads();

    if (t < NCC) {
        float s = bp[t];
        for (int h = 0; h < HIDD; h++) s += mid[h] * Wp[h * NCC + t];
        logits[t] = s;
    }
    __syncthreads();

    if (t == 0) {
        float mx = logits[0];
        for (int c = 1; c < NCC; c++) mx = fmaxf(mx, logits[c]);
        float sum = 0.f;
        for (int c = 0; c < NCC; c++) sum += expf(logits[c] - mx);
        float lse = mx + logf(sum);
        for (int c = 0; c < NCC; c++) out[q * NCC + c] = logits[c] - lse;
    }
}

// ---------------------------------------------------------------------------
extern "C" void kernel_launch(void* const* d_in, const int* in_sizes, int n_in,
                              void* d_out, int out_size)
{
    (void)n_in; (void)out_size;
    const int*   ltok  = (const int*)d_in[0];
    const int*   rtok  = (const int*)d_in[1];
    const float* emb   = (const float*)d_in[2];
    const float* Wioux = (const float*)d_in[3];
    const float* bioux = (const float*)d_in[4];
    const float* Wiouh = (const float*)d_in[5];
    const float* biouh = (const float*)d_in[6];
    // d_in[7] = Wfx, d_in[8] = bfx : unused by the reference computation
    const float* Wfh   = (const float*)d_in[9];
    const float* bfh   = (const float*)d_in[10];
    const float* Wh    = (const float*)d_in[11];
    const float* bh    = (const float*)d_in[12];
    const float* Wp    = (const float*)d_in[13];
    const float* bp    = (const float*)d_in[14];
    float* out = (float*)d_out;

    int V = in_sizes[2] / IND;
    if (V > VMAX) V = VMAX;

    void* p;
    float *hA, *cA, *hB, *cB, *hc, *iouh, *fc;
    cudaGetSymbolAddress(&p, g_hc);   hc   = (float*)p;
    cudaGetSymbolAddress(&p, g_iouh); iouh = (float*)p;
    cudaGetSymbolAddress(&p, g_fc);   fc   = (float*)p;
    cudaGetSymbolAddress(&p, g_hA); hA = (float*)p;
    cudaGetSymbolAddress(&p, g_cA); cA = (float*)p;
    cudaGetSymbolAddress(&p, g_hB); hB = (float*)p;
    cudaGetSymbolAddress(&p, g_cB); cB = (float*)p;

    const int vocab_smem = 14464 * 4;   // 57856 B
    static int attr_done = 0;
    if (!attr_done) {
        cudaFuncSetAttribute(vocab_kernel, cudaFuncAttributeMaxDynamicSharedMemorySize, vocab_smem);
        cudaFuncSetAttribute(tree_kernel,   cudaFuncAttributePreferredSharedMemoryCarveout, 100);
        cudaFuncSetAttribute(vocab2_kernel, cudaFuncAttributePreferredSharedMemoryCarveout, 100);
        attr_done = 1;
    }

    // 0) Weight layout prep
    prep_kernel<<<(M * 750 + M * 600 + IND * M3 + 255) / 256, 256>>>(Wiouh, Wfh, Wioux);

    // 1) Vocab GEMM + fused gates: g_hc[v] = (h(v), c(v))
    vocab_kernel<<<(V + VRT - 1) / VRT, 256, vocab_smem>>>(emb, bioux, biouh, hc, V);

    // 2) Vocab2 GEMM: iouh[v] = h(v)@Wiouh ; fc[v] = sig(h(v)@Wfh+bfh)*c(v)
    vocab2_kernel<<<(V + TRT - 1) / TRT, 320>>>(hc, iouh, fc, bfh, V);

    // 3) Tree level 1 — pure gather/elementwise (no GEMM), float2 path
    leaf1_kernel<<<(BQ * (LVS / 2) * (M / 2)) / 256, 256>>>(
        ltok, rtok, iouh, fc, biouh, hA, cA);

    // 4) Tree levels 2..6, ping-pong A <-> B
    const float* hin = hA; const float* cin = cA;
    float* ho = hB; float* co = cB;
    for (int n_out = LVS / 4; n_out >= 1; n_out >>= 1) {
        tree_kernel<<<(BQ * n_out) / TRT, 256>>>(hin, cin, ho, co, biouh, bfh);
        const float* th = hin; const float* tc = cin;
        hin = ho; cin = co;
        ho = (float*)th; co = (float*)tc;
    }

    // 5) Classifier
    cls_kernel<<<BH, 64>>>(hin, Wh, bh, Wp, bp, out);
}

// round 14
// speedup vs baseline: 1.1321x; 1.0121x over previous
#include <cuda_runtime.h>
#include <math.h>

// Problem constants
#define BQ   4096     // both sides fused: [0,2048)=left, [2048,4096)=right
#define BH   2048
#define LVS  64
#define IND  300
#define M    150
#define M3   450
#define HIDD 50
#define NCC  5
#define VMAX 50000

#define TRT  16       // rows per block (tree + vocab2)
#define VRT  32       // rows per block (vocab GEMM)

// Scratch (uninitialized __device__ globals: no runtime allocation)
__device__ __align__(16) float g_hc[VMAX * 2 * M];   // 60 MB: [v][0:150]=h, [150:300]=c
__device__ __align__(16) float g_iouh[VMAX * M3];    // 90 MB: h(v)@Wiouh
__device__ __align__(16) float g_fc[VMAX * M];       // 30 MB: sig(h(v)@Wfh+bfh)*c(v)
__device__ __align__(16) float g_hA[BQ * (LVS / 2) * M];
__device__ __align__(16) float g_cA[BQ * (LVS / 2) * M];
__device__ __align__(16) float g_hB[BQ * (LVS / 4) * M];
__device__ __align__(16) float g_cB[BQ * (LVS / 4) * M];
__device__ __align__(16) float g_WP[M * 3 * 256];    // tree weights plane-split (750 fused cols)
__device__ __align__(16) float g_WP2[M * 640];       // vocab2 weights 2-plane split (600 fused cols, stride 320)
__device__ __align__(16) float g_WdupX[IND * 900];   // vocab: [k][450 cols x2]

__device__ __forceinline__ float sigf(float x)  { return 1.0f / (1.0f + __expf(-x)); }
__device__ __forceinline__ float tanhf_(float x){ return 1.0f - 2.0f / (__expf(2.0f * x) + 1.0f); }

// ---- packed f32x2 helpers (sm_100+) --------------------------------------
__device__ __forceinline__ void ffma2(unsigned long long& acc,
                                      unsigned long long a,
                                      unsigned long long b) {
    asm("fma.rn.f32x2 %0, %1, %2, %0;" : "+l"(acc) : "l"(a), "l"(b));
}
__device__ __forceinline__ unsigned long long pack2(float x, float y) {
    unsigned long long r;
    asm("mov.b64 %0, {%1, %2};" : "=l"(r) : "f"(x), "f"(y));
    return r;
}
__device__ __forceinline__ float2 unpack2(unsigned long long v) {
    float2 f;
    asm("mov.b64 {%0, %1}, %2;" : "=f"(f.x), "=f"(f.y) : "l"(v));
    return f;
}

// ---------------------------------------------------------------------------
// Prep: plane-split weights.
// ---------------------------------------------------------------------------
__global__ void __launch_bounds__(256) prep_kernel(
    const float* __restrict__ Wiouh, const float* __restrict__ Wfh,
    const float* __restrict__ Wioux)
{
    int idx = blockIdx.x * 256 + threadIdx.x;
    const int NT  = M * 750;          // 112500
    const int NT2 = M * 600;          // 90000
    const int NX  = IND * M3;         // 135000
    if (idx < NT) {
        int k = idx / 750, c = idx - k * 750;
        float w = (c < M3) ? Wiouh[k * M3 + c]
                           : Wfh[k * M + (c >= 600 ? c - 600 : c - 450)];
        int t = c / 3, p = c - 3 * t;
        g_WP[(k * 3 + p) * 256 + t] = w;
    } else if (idx < NT + NT2) {
        int j = idx - NT;
        int k = j / 600, c = j - k * 600;
        float w = (c < M3) ? Wiouh[k * M3 + c] : Wfh[k * M + (c - 450)];
        int t = c >> 1, p = c & 1;
        g_WP2[(k * 2 + p) * 320 + t] = w;
    } else if (idx < NT + NT2 + NX) {
        int j = idx - NT - NT2;
        int k = j / M3, c = j - k * M3;
        float w = Wioux[k * M3 + c];
        g_WdupX[k * 900 + 2 * c]     = w;
        g_WdupX[k * 900 + 2 * c + 1] = w;
    }
}

// ---------------------------------------------------------------------------
// Vocab GEMM + gates fused. 256 threads, 32 rows.
// ---------------------------------------------------------------------------
__global__ void __launch_bounds__(256, 2) vocab_kernel(
    const float* __restrict__ emb,
    const float* __restrict__ bx, const float* __restrict__ bhh,
    float* __restrict__ hc, int V)
{
    extern __shared__ __align__(16) float sm[];
    float* xs = sm;                    // [k*36 + rr]

    const int t = threadIdx.x;
    const int base = blockIdx.x * VRT;

    for (int idx = t; idx < VRT * IND; idx += 256) {
        int rr = idx / IND, k = idx - rr * IND;
        int row = base + rr;
        if (row >= V) row = V - 1;
        xs[k * 36 + rr] = emb[row * IND + k];
    }
    __syncthreads();

    unsigned long long a0[16], a1[16];
#pragma unroll
    for (int i = 0; i < 16; i++) { a0[i] = 0ull; a1[i] = 0ull; }

    const bool has1 = (t + 256) < M3;   // t < 194
    const float* __restrict__ wbase0 = g_WdupX + 2 * t;
    const float* __restrict__ wbase1 = g_WdupX + (has1 ? 2 * (t + 256) : 0);

#pragma unroll 2
    for (int k = 0; k < IND; k++) {
        unsigned long long pw0 = *reinterpret_cast<const unsigned long long*>(wbase0 + k * 900);
        unsigned long long pw1 = *reinterpret_cast<const unsigned long long*>(wbase1 + k * 900);
        const ulonglong2* xp = reinterpret_cast<const ulonglong2*>(xs + k * 36);
#pragma unroll
        for (int p = 0; p < 8; p++) {
            ulonglong2 v = xp[p];                 // rows 4p..4p+3
            ffma2(a0[2 * p],     v.x, pw0);
            ffma2(a0[2 * p + 1], v.y, pw0);
            ffma2(a1[2 * p],     v.x, pw1);
            ffma2(a1[2 * p + 1], v.y, pw1);
        }
    }
    __syncthreads();   // xs consumed; reuse sm as iou[rr][452]

    float b0 = bx[t] + bhh[t];
    float b1 = has1 ? (bx[t + 256] + bhh[t + 256]) : 0.f;
#pragma unroll
    for (int pr = 0; pr < 16; pr++) {
        float2 v0 = unpack2(a0[pr]);
        sm[(2 * pr) * 452 + t]     = v0.x + b0;
        sm[(2 * pr + 1) * 452 + t] = v0.y + b0;
        if (has1) {
            float2 v1 = unpack2(a1[pr]);
            sm[(2 * pr) * 452 + t + 256]     = v1.x + b1;
            sm[(2 * pr + 1) * 452 + t + 256] = v1.y + b1;
        }
    }
    __syncthreads();

    for (int idx = t; idx < VRT * M; idx += 256) {
        int rr = idx / M, j = idx - rr * M;
        int row = base + rr;
        if (row < V) {
            const float* r = sm + rr * 452;
            float iv = sigf(r[j]);
            float ov = sigf(r[j + M]);
            float uv = tanhf_(r[j + 2 * M]);
            float cv = iv * uv;
            float hv = ov * tanhf_(cv);
            hc[row * 2 * M + j]     = hv;
            hc[row * 2 * M + M + j] = cv;
        }
    }
}

// ---------------------------------------------------------------------------
// Vocab2 GEMM — 320 threads, 16 rows, 2 slots/thread, explicit weight
// prefetch (1 iteration ahead) to hide the L2-hit LDG latency.
// ---------------------------------------------------------------------------
__global__ void __launch_bounds__(320, 3) vocab2_kernel(
    const float* __restrict__ hc,
    float* __restrict__ iouh, float* __restrict__ fcout,
    const float* __restrict__ bfh, int V)
{
    __shared__ __align__(16) float sm[9728];   // tile 3000 fl, then res 16x604
    const int t = threadIdx.x;
    const int base = blockIdx.x * TRT;

    float* HT = sm;            // [k*20 + rr]
    for (int idx = t; idx < TRT * M; idx += 320) {
        int rr = idx / M, k = idx - rr * M;
        int row = base + rr;
        if (row >= V) row = V - 1;
        HT[k * 20 + rr] = hc[row * 2 * M + k];
    }
    __syncthreads();

    const int slot0 = 2 * t;
    const bool active = slot0 < 600;   // t < 300
    const float* __restrict__ wp = g_WP2 + (active ? t : 0);

    unsigned long long a0[8], a1[8];
#pragma unroll
    for (int i = 0; i < 8; i++) { a0[i] = 0ull; a1[i] = 0ull; }

    float w0n = wp[0];
    float w1n = wp[320];
#pragma unroll 2
    for (int k = 0; k < M; k++) {
        float w0 = w0n, w1 = w1n;
        if (k + 1 < M) {
            const float* wk = wp + (k + 1) * 640;
            w0n = wk[0];
            w1n = wk[320];
        }
        unsigned long long pw0 = pack2(w0, w0);
        unsigned long long pw1 = pack2(w1, w1);
        const ulonglong2* tp = reinterpret_cast<const ulonglong2*>(HT + k * 20);
#pragma unroll
        for (int p = 0; p < 4; p++) {
            ulonglong2 v = tp[p];
            ffma2(a0[2 * p],     v.x, pw0);
            ffma2(a0[2 * p + 1], v.y, pw0);
            ffma2(a1[2 * p],     v.x, pw1);
            ffma2(a1[2 * p + 1], v.y, pw1);
        }
    }
    __syncthreads();   // tile consumed; reuse sm as res[rr][604]

    if (active) {
#pragma unroll
        for (int p = 0; p < 8; p++) {
            float2 v0 = unpack2(a0[p]);
            float2 v1 = unpack2(a1[p]);
            float* r0 = sm + (2 * p) * 604;
            float* r1 = sm + (2 * p + 1) * 604;
            r0[slot0]     = v0.x;  r1[slot0]     = v0.y;
            r0[slot0 + 1] = v1.x;  r1[slot0 + 1] = v1.y;
        }
    }
    __syncthreads();

    for (int idx = t; idx < TRT * M3; idx += 320) {
        int rr = idx / M3, j = idx - rr * M3;
        int row = base + rr;
        if (row < V) iouh[row * M3 + j] = sm[rr * 604 + j];
    }
    for (int idx = t; idx < TRT * M; idx += 320) {
        int rr = idx / M, j = idx - rr * M;
        int row = base + rr;
        if (row < V) {
            float f = sigf(sm[rr * 604 + 450 + j] + bfh[j]);
            fcout[row * M + j] = f * hc[row * 2 * M + M + j];
        }
    }
}

// ---------------------------------------------------------------------------
// Leaf level (tree level 1) — NO GEMM, float2-vectorized.
// ---------------------------------------------------------------------------
__global__ void __launch_bounds__(256) leaf1_kernel(
    const int* __restrict__ ltok, const int* __restrict__ rtok,
    const float* __restrict__ iouh, const float* __restrict__ fc,
    const float* __restrict__ biouh,
    float* __restrict__ h_out, float* __restrict__ c_out)
{
    int idx = blockIdx.x * 256 + threadIdx.x;     // < BQ*32*75
    int row = idx / 75;
    int j2 = idx - row * 75;                      // float2 index within row
    int j = 2 * j2;
    int q = row >> 5, n = row & 31;
    const int* toks = (q < BH) ? (ltok + q * LVS) : (rtok + (q - BH) * LVS);
    int t0 = toks[2 * n], t1 = toks[2 * n + 1];
    const float2* i0 = reinterpret_cast<const float2*>(iouh + t0 * M3);
    const float2* i1 = reinterpret_cast<const float2*>(iouh + t1 * M3);
    float2 ai = i0[j2],       bi = i1[j2];
    float2 ao = i0[j2 + 75],  bo = i1[j2 + 75];
    float2 au = i0[j2 + 150], bu = i1[j2 + 150];
    float2 f0v = *reinterpret_cast<const float2*>(fc + t0 * M + j);
    float2 f1v = *reinterpret_cast<const float2*>(fc + t1 * M + j);
    float2 bbi = *reinterpret_cast<const float2*>(biouh + j);
    float2 bbo = *reinterpret_cast<const float2*>(biouh + M + j);
    float2 bbu = *reinterpret_cast<const float2*>(biouh + 2 * M + j);

    float2 cv, hv;
    {
        float iv = sigf(ai.x + bi.x + bbi.x);
        float ov = sigf(ao.x + bo.x + bbo.x);
        float uv = tanhf_(au.x + bu.x + bbu.x);
        cv.x = iv * uv + f0v.x + f1v.x;
        hv.x = ov * tanhf_(cv.x);
    }
    {
        float iv = sigf(ai.y + bi.y + bbi.y);
        float ov = sigf(ao.y + bo.y + bbo.y);
        float uv = tanhf_(au.y + bu.y + bbu.y);
        cv.y = iv * uv + f0v.y + f1v.y;
        hv.y = ov * tanhf_(cv.y);
    }
    *reinterpret_cast<float2*>(c_out + row * M + j) = cv;
    *reinterpret_cast<float2*>(h_out + row * M + j) = hv;
}

// ---------------------------------------------------------------------------
// Tree level kernel (levels 2..6) — 256 thr, 16 rows, 3 slots/thread,
// 3 blocks/SM, explicit weight prefetch (1 iteration ahead).
// Fused 750 cols: [0,450)=iou(hs), [450,600)=f0, [600,750)=f1.
// ---------------------------------------------------------------------------
__global__ void __launch_bounds__(256, 3) tree_kernel(
    const float* __restrict__ h_in, const float* __restrict__ c_in,
    float* __restrict__ h_out, float* __restrict__ c_out,
    const float* __restrict__ biouh, const float* __restrict__ bfh)
{
    __shared__ __align__(16) float sm[12096];   // 48384 B
    const int t = threadIdx.x;
    const int base = blockIdx.x * TRT;

    float* HS = sm;            // [k*20 + rr]
    float* H0 = sm + 3000;
    float* H1 = sm + 6000;

    for (int idx = t; idx < TRT * M; idx += 256) {
        int rr = idx / M, k = idx - rr * M;
        int orow = base + rr;
        float a = h_in[(2 * orow) * M + k];
        float b = h_in[(2 * orow + 1) * M + k];
        HS[k * 20 + rr] = a + b;
        H0[k * 20 + rr] = a;
        H1[k * 20 + rr] = b;
    }
    __syncthreads();

    const int slot0 = 3 * t;
    const bool active = slot0 < 750;
    const int region = (slot0 < 450) ? 0 : ((slot0 < 600) ? 1 : 2);
    const float* tile = (region == 0) ? HS : ((region == 1) ? H0 : H1);
    const float* __restrict__ wp = g_WP + (active ? t : 0);

    unsigned long long a0[8], a1[8], a2[8];
#pragma unroll
    for (int i = 0; i < 8; i++) { a0[i] = 0ull; a1[i] = 0ull; a2[i] = 0ull; }

    float w0n = wp[0];
    float w1n = wp[256];
    float w2n = wp[512];
#pragma unroll 2
    for (int k = 0; k < M; k++) {
        float w0 = w0n, w1 = w1n, w2 = w2n;
        if (k + 1 < M) {
            const float* wk = wp + (k + 1) * 768;
            w0n = wk[0];
            w1n = wk[256];
            w2n = wk[512];
        }
        unsigned long long pw0 = pack2(w0, w0);
        unsigned long long pw1 = pack2(w1, w1);
        unsigned long long pw2 = pack2(w2, w2);
        const ulonglong2* tp = reinterpret_cast<const ulonglong2*>(tile + k * 20);
#pragma unroll
        for (int p = 0; p < 4; p++) {
            ulonglong2 v = tp[p];                 // rows 4p..4p+3 (broadcast)
            ffma2(a0[2 * p],     v.x, pw0);
            ffma2(a0[2 * p + 1], v.y, pw0);
            ffma2(a1[2 * p],     v.x, pw1);
            ffma2(a1[2 * p + 1], v.y, pw1);
            ffma2(a2[2 * p],     v.x, pw2);
            ffma2(a2[2 * p + 1], v.y, pw2);
        }
    }
    __syncthreads();   // tiles fully consumed; reuse sm as res[rr][756]

    if (active) {
        float bb0, bb1, bb2;
        if (region == 0)      { bb0 = biouh[slot0];     bb1 = biouh[slot0 + 1]; bb2 = biouh[slot0 + 2]; }
        else if (region == 1) { bb0 = bfh[slot0 - 450]; bb1 = bfh[slot0 - 449]; bb2 = bfh[slot0 - 448]; }
        else                  { bb0 = bfh[slot0 - 600]; bb1 = bfh[slot0 - 599]; bb2 = bfh[slot0 - 598]; }
#pragma unroll
        for (int p = 0; p < 8; p++) {
            float2 v0 = unpack2(a0[p]);
            float2 v1 = unpack2(a1[p]);
            float2 v2 = unpack2(a2[p]);
            float* r0 = sm + (2 * p) * 756;
            float* r1 = sm + (2 * p + 1) * 756;
            r0[slot0]     = v0.x + bb0;  r1[slot0]     = v0.y + bb0;
            r0[slot0 + 1] = v1.x + bb1;  r1[slot0 + 1] = v1.y + bb1;
            r0[slot0 + 2] = v2.x + bb2;  r1[slot0 + 2] = v2.y + bb2;
        }
    }
    __syncthreads();

    for (int idx = t; idx < TRT * M; idx += 256) {
        int rr = idx / M, j = idx - rr * M;
        const float* r = sm + rr * 756;
        float iv = sigf(r[j]);
        float ov = sigf(r[j + 150]);
        float uv = tanhf_(r[j + 300]);
        float f0 = sigf(r[450 + j]);
        float f1 = sigf(r[600 + j]);
        int orow = base + rr;
        float c0 = c_in[(2 * orow) * M + j];
        float c1 = c_in[(2 * orow + 1) * M + j];
        float cv = iv * uv + f0 * c0 + f1 * c1;
        float hv = ov * tanhf_(cv);
        c_out[orow * M + j] = cv;
        h_out[orow * M + j] = hv;
    }
}

// ---------------------------------------------------------------------------
// Classifier — 4-way ILP in the mid GEMV (breaks the 300-long dependent
// FFMA chain that serialized the old version).
// ---------------------------------------------------------------------------
__global__ void __launch_bounds__(64) cls_kernel(
    const float* __restrict__ hfin,
    const float* __restrict__ Wh, const float* __restrict__ bh,
    const float* __restrict__ Wp, const float* __restrict__ bp,
    float* __restrict__ out)
{
    __shared__ float vec[2 * M];
    __shared__ float mid[HIDD];
    __shared__ float logits[NCC];

    const int q = blockIdx.x;
    const int t = threadIdx.x;
    const float* lh = hfin + q * M;
    const float* rh = hfin + (BH + q) * M;

    for (int j = t; j < M; j += 64) {
        float a = lh[j], b = rh[j];
        vec[j]     = a * b;
        vec[M + j] = fabsf(a - b);
    }
    __syncthreads();

    if (t < HIDD) {
        float s0 = 0.f, s1 = 0.f, s2 = 0.f, s3 = 0.f;
#pragma unroll 4
        for (int j = 0; j < 2 * M; j += 4) {
            s0 += vec[j]     * Wh[j * HIDD + t];
            s1 += vec[j + 1] * Wh[(j + 1) * HIDD + t];
            s2 += vec[j + 2] * Wh[(j + 2) * HIDD + t];
            s3 += vec[j + 3] * Wh[(j + 3) * HIDD + t];
        }
        mid[t] = sigf(bh[t] + ((s0 + s1) + (s2 + s3)));
    }
    __syncthreads();

    if (t < NCC) {
        float s = bp[t];
        for (int h = 0; h < HIDD; h++) s += mid[h] * Wp[h * NCC + t];
        logits[t] = s;
    }
    __syncthreads();

    if (t == 0) {
        float mx = logits[0];
        for (int c = 1; c < NCC; c++) mx = fmaxf(mx, logits[c]);
        float sum = 0.f;
        for (int c = 0; c < NCC; c++) sum += expf(logits[c] - mx);
        float lse = mx + logf(sum);
        for (int c = 0; c < NCC; c++) out[q * NCC + c] = logits[c] - lse;
    }
}

// ---------------------------------------------------------------------------
extern "C" void kernel_launch(void* const* d_in, const int* in_sizes, int n_in,
                              void* d_out, int out_size)
{
    (void)n_in; (void)out_size;
    const int*   ltok  = (const int*)d_in[0];
    const int*   rtok  = (const int*)d_in[1];
    const float* emb   = (const float*)d_in[2];
    const float* Wioux = (const float*)d_in[3];
    const float* bioux = (const float*)d_in[4];
    const float* Wiouh = (const float*)d_in[5];
    const float* biouh = (const float*)d_in[6];
    // d_in[7] = Wfx, d_in[8] = bfx : unused by the reference computation
    const float* Wfh   = (const float*)d_in[9];
    const float* bfh   = (const float*)d_in[10];
    const float* Wh    = (const float*)d_in[11];
    const float* bh    = (const float*)d_in[12];
    const float* Wp    = (const float*)d_in[13];
    const float* bp    = (const float*)d_in[14];
    float* out = (float*)d_out;

    int V = in_sizes[2] / IND;
    if (V > VMAX) V = VMAX;

    void* p;
    float *hA, *cA, *hB, *cB, *hc, *iouh, *fc;
    cudaGetSymbolAddress(&p, g_hc);   hc   = (float*)p;
    cudaGetSymbolAddress(&p, g_iouh); iouh = (float*)p;
    cudaGetSymbolAddress(&p, g_fc);   fc   = (float*)p;
    cudaGetSymbolAddress(&p, g_hA); hA = (float*)p;
    cudaGetSymbolAddress(&p, g_cA); cA = (float*)p;
    cudaGetSymbolAddress(&p, g_hB); hB = (float*)p;
    cudaGetSymbolAddress(&p, g_cB); cB = (float*)p;

    const int vocab_smem = 14464 * 4;   // 57856 B
    static int attr_done = 0;
    if (!attr_done) {
        cudaFuncSetAttribute(vocab_kernel, cudaFuncAttributeMaxDynamicSharedMemorySize, vocab_smem);
        cudaFuncSetAttribute(tree_kernel,   cudaFuncAttributePreferredSharedMemoryCarveout, 100);
        cudaFuncSetAttribute(vocab2_kernel, cudaFuncAttributePreferredSharedMemoryCarveout, 100);
        attr_done = 1;
    }

    // 0) Weight layout prep
    prep_kernel<<<(M * 750 + M * 600 + IND * M3 + 255) / 256, 256>>>(Wiouh, Wfh, Wioux);

    // 1) Vocab GEMM + fused gates: g_hc[v] = (h(v), c(v))
    vocab_kernel<<<(V + VRT - 1) / VRT, 256, vocab_smem>>>(emb, bioux, biouh, hc, V);

    // 2) Vocab2 GEMM: iouh[v] = h(v)@Wiouh ; fc[v] = sig(h(v)@Wfh+bfh)*c(v)
    vocab2_kernel<<<(V + TRT - 1) / TRT, 320>>>(hc, iouh, fc, bfh, V);

    // 3) Tree level 1 — pure gather/elementwise (no GEMM), float2 path
    leaf1_kernel<<<(BQ * (LVS / 2) * (M / 2)) / 256, 256>>>(
        ltok, rtok, iouh, fc, biouh, hA, cA);

    // 4) Tree levels 2..6, ping-pong A <-> B
    const float* hin = hA; const float* cin = cA;
    float* ho = hB; float* co = cB;
    for (int n_out = LVS / 4; n_out >= 1; n_out >>= 1) {
        tree_kernel<<<(BQ * n_out) / TRT, 256>>>(hin, cin, ho, co, biouh, bfh);
        const float* th = hin; const float* tc = cin;
        hin = ho; cin = co;
        ho = (float*)th; co = (float*)tc;
    }

    // 5) Classifier
    cls_kernel<<<BH, 64>>>(hin, Wh, bh, Wp, bp, out);
}